// round 14
// baseline (speedup 1.0000x reference)
#include <cuda_runtime.h>
#include <cuda_bf16.h>
#include <cstdint>

#define N_NODES 100000
#define IN_CH   128
#define OUT_TOT 128
#define N_EDGES 1600000
#define N_MASKW 3125          // 100000/32 exactly

#define BM 64
#define NT 256
#define RS 136                // smem row stride in bf16 elems (272B, LDSM conflict-free)
#define N_TILES ((N_NODES + BM - 1) / BM)   // 1563
#define GRID_P 296            // persistent CTAs: 2 per SM x 148

// SMEM layout (dynamic)
#define SM_MASK 0             // 2 x u32
#define SM_AH   32
#define SM_AL   (SM_AH + BM * RS * 2)      // +17408
#define SM_BH   (SM_AL + BM * RS * 2)
#define SM_BL   (SM_BH + 128 * RS * 2)     // +34816
#define SM_TOTAL (SM_BL + 128 * RS * 2)    // 104,480 bytes -> 2 CTAs/SM

// Per-node indegree bitmask. Zero at module load; GEMM re-clears its own
// words every launch => graph-replay deterministic.
__device__ unsigned g_maskw[N_MASKW];
// Preconverted B (hi/lo bf16), rewritten identically every launch.
__device__ __nv_bfloat16 g_Bh[128 * 128];
__device__ __nv_bfloat16 g_Bl[128 * 128];

// ---------------- helpers ----------------
__device__ __forceinline__ uint32_t smem_u32(const void* p) {
    uint32_t a;
    asm("{ .reg .u64 t; cvta.to.shared.u64 t, %1; cvt.u32.u64 %0, t; }" : "=r"(a) : "l"(p));
    return a;
}
__device__ __forceinline__ void ldsm_x4(uint32_t (&r)[4], uint32_t addr) {
    asm volatile("ldmatrix.sync.aligned.m8n8.x4.shared.b16 {%0,%1,%2,%3}, [%4];"
                 : "=r"(r[0]), "=r"(r[1]), "=r"(r[2]), "=r"(r[3]) : "r"(addr));
}
__device__ __forceinline__ void ldsm_x4_t(uint32_t (&r)[4], uint32_t addr) {
    asm volatile("ldmatrix.sync.aligned.m8n8.x4.trans.shared.b16 {%0,%1,%2,%3}, [%4];"
                 : "=r"(r[0]), "=r"(r[1]), "=r"(r[2]), "=r"(r[3]) : "r"(addr));
}
__device__ __forceinline__ void mma_bf16(float (&d)[4], const uint32_t (&a)[4],
                                         uint32_t b0, uint32_t b1) {
    asm volatile(
        "mma.sync.aligned.m16n8k16.row.col.f32.bf16.bf16.f32 "
        "{%0,%1,%2,%3}, {%4,%5,%6,%7}, {%8,%9}, {%0,%1,%2,%3};"
        : "+f"(d[0]), "+f"(d[1]), "+f"(d[2]), "+f"(d[3])
        : "r"(a[0]), "r"(a[1]), "r"(a[2]), "r"(a[3]), "r"(b0), "r"(b1));
}
__device__ __forceinline__ void split1(float x, unsigned short& h, unsigned short& l) {
    __nv_bfloat16 bh = __float2bfloat16(x);
    float r = x - __bfloat162float(bh);
    __nv_bfloat16 bl = __float2bfloat16(r);
    h = __bfloat16_as_ushort(bh);
    l = __bfloat16_as_ushort(bl);
}

// ------- mask scatter (SMEM bitmask -> L2 merge) + B split preconvert -------
__global__ __launch_bounds__(NT) void mask_scatter_kernel(const int* __restrict__ col,
                                                          const float* __restrict__ B) {
    __shared__ unsigned s_bits[N_MASKW];
    int tid = threadIdx.x;

    int gi = blockIdx.x * NT + tid;
    if (gi < 128 * 128) {
        unsigned short h, l;
        split1(B[gi], h, l);
        g_Bh[gi] = __ushort_as_bfloat16(h);
        g_Bl[gi] = __ushort_as_bfloat16(l);
    }

    for (int i = tid; i < N_MASKW; i += NT) s_bits[i] = 0u;
    __syncthreads();

    int per = (N_EDGES + gridDim.x - 1) / gridDim.x;
    int start = blockIdx.x * per;
    int end = start + per; if (end > N_EDGES) end = N_EDGES;
    for (int i = start + tid; i < end; i += NT) {
        unsigned c = (unsigned)col[i];
        if (c < N_NODES) atomicOr(&s_bits[c >> 5], 1u << (c & 31));
    }
    __syncthreads();
    for (int i = tid; i < N_MASKW; i += NT) {
        unsigned w = s_bits[i];
        if (w) atomicOr(&g_maskw[i], w);
    }
}

// ---- A-tile register prefetch: 8 float4 per thread (rows of tile `t`) ----
__device__ __forceinline__ void load_A_regs(const float* __restrict__ A, int row0,
                                            int tid, float4 (&pref)[8]) {
#pragma unroll
    for (int i = 0; i < 8; i++) {
        int idx = tid + i * NT;          // 0..2047
        int m  = idx >> 5;               // 0..63
        int k0 = (idx & 31) * 4;
        int gr = row0 + m;
        float4 v = make_float4(0.f, 0.f, 0.f, 0.f);
        if (gr < N_NODES)
            v = *reinterpret_cast<const float4*>(A + (size_t)gr * IN_CH + k0);
        pref[i] = v;
    }
}

// ---------------- persistent pipelined GEMM: C[n,:] = mask[n] ? A[n,:] @ B : 0 ----------------
__global__ __launch_bounds__(NT, 2) void gat_gemm_mma(
    const float* __restrict__ A, float* __restrict__ C)
{
    extern __shared__ char smem[];
    const uint32_t sb = smem_u32(smem);
    const int tid = threadIdx.x;
    const int lane = tid & 31;
    const int wid = tid >> 5;

    // ---- B tiles into SMEM once per CTA (bf16, preconverted) ----
#pragma unroll
    for (int i = 0; i < 8; i++) {
        int idx = tid + i * NT;
        int k  = idx >> 4;               // 0..127
        int n0 = (idx & 15) * 8;
        int soff = (k * RS + n0) * 2;
        *reinterpret_cast<uint4*>(smem + SM_BH + soff) =
            *reinterpret_cast<const uint4*>(&g_Bh[k * OUT_TOT + n0]);
        *reinterpret_cast<uint4*>(smem + SM_BL + soff) =
            *reinterpret_cast<const uint4*>(&g_Bl[k * OUT_TOT + n0]);
    }

    const int wm = wid & 1;
    const int wn = wid >> 1;
    const int rbase = wm * 32;
    const int cbase = wn * 32;
    const uint32_t aoff = (uint32_t)((rbase + (lane & 15)) * RS + 8 * (lane >> 4)) * 2;
    const uint32_t boff = (uint32_t)((lane & 15) * RS + cbase + 8 * (lane >> 4)) * 2;
    const uint32_t aBaseH = sb + SM_AH + aoff, aBaseL = sb + SM_AL + aoff;
    const uint32_t bBaseH = sb + SM_BH + boff, bBaseL = sb + SM_BL + boff;
    const unsigned* mw = reinterpret_cast<const unsigned*>(smem + SM_MASK);
    const int group = lane >> 2;
    const int tc = lane & 3;

    // ---- Pipeline prologue: prefetch first tile ----
    float4 pref[8];
    unsigned prefMask = 0;
    int tile = blockIdx.x;
    if (tile < N_TILES) {
        load_A_regs(A, tile * BM, tid, pref);
        if (tid < 2) {
            int w = tile * (BM / 32) + tid;
            if (w < N_MASKW) { prefMask = g_maskw[w]; g_maskw[w] = 0u; }
        }
    }

    for (; tile < N_TILES; tile += GRID_P) {
        const int row0 = tile * BM;

        // ---- Convert prefetched A regs -> smem; publish mask ----
        if (tid < 2) reinterpret_cast<unsigned*>(smem + SM_MASK)[tid] = prefMask;
#pragma unroll
        for (int i = 0; i < 8; i++) {
            int idx = tid + i * NT;
            int m  = idx >> 5;
            int k0 = (idx & 31) * 4;
            float4 v = pref[i];
            unsigned short h0, h1, h2, h3, l0, l1, l2, l3;
            split1(v.x, h0, l0); split1(v.y, h1, l1);
            split1(v.z, h2, l2); split1(v.w, h3, l3);
            uint2 hh = make_uint2((unsigned)h0 | ((unsigned)h1 << 16),
                                  (unsigned)h2 | ((unsigned)h3 << 16));
            uint2 ll = make_uint2((unsigned)l0 | ((unsigned)l1 << 16),
                                  (unsigned)l2 | ((unsigned)l3 << 16));
            int off = (m * RS + k0) * 2;
            *reinterpret_cast<uint2*>(smem + SM_AH + off) = hh;
            *reinterpret_cast<uint2*>(smem + SM_AL + off) = ll;
        }
        __syncthreads();

        // ---- Prefetch NEXT tile (LDG latency hides under MMA below) ----
        int next = tile + GRID_P;
        if (next < N_TILES) {
            load_A_regs(A, next * BM, tid, pref);
            if (tid < 2) {
                int w = next * (BM / 32) + tid;
                prefMask = 0;
                if (w < N_MASKW) { prefMask = g_maskw[w]; g_maskw[w] = 0u; }
            }
        }

        // ---- MMA phase ----
        float acc[2][4][4];
#pragma unroll
        for (int mi = 0; mi < 2; mi++)
#pragma unroll
            for (int n8 = 0; n8 < 4; n8++)
#pragma unroll
                for (int q = 0; q < 4; q++) acc[mi][n8][q] = 0.f;

#pragma unroll
        for (int p = 0; p < 3; p++) {          // AhBh, AhBl, AlBh
            const uint32_t aB = (p == 2) ? aBaseL : aBaseH;
            const uint32_t bB = (p == 1) ? bBaseL : bBaseH;
#pragma unroll
            for (int ks = 0; ks < 8; ks++) {
                uint32_t a[2][4], b[2][4];
                ldsm_x4(a[0], aB + 2 * (ks * 16));
                ldsm_x4(a[1], aB + 2 * (16 * RS + ks * 16));
                ldsm_x4_t(b[0], bB + 2 * (ks * 16 * RS));
                ldsm_x4_t(b[1], bB + 2 * (ks * 16 * RS + 16));
#pragma unroll
                for (int mi = 0; mi < 2; mi++)
#pragma unroll
                    for (int n8 = 0; n8 < 4; n8++)
                        mma_bf16(acc[mi][n8], a[mi],
                                 b[n8 >> 1][(n8 & 1) * 2], b[n8 >> 1][(n8 & 1) * 2 + 1]);
            }
        }

        // ---- Epilogue ----
#pragma unroll
        for (int mi = 0; mi < 2; mi++) {
#pragma unroll
            for (int half = 0; half < 2; half++) {
                int rloc = rbase + mi * 16 + group + half * 8;
                int r = row0 + rloc;
                float mv = ((mw[rloc >> 5] >> (rloc & 31)) & 1u) ? 1.0f : 0.0f;
                if (r < N_NODES) {
                    float* cp = C + (size_t)r * OUT_TOT + cbase + tc * 2;
#pragma unroll
                    for (int n8 = 0; n8 < 4; n8++) {
                        float2 o;
                        o.x = acc[mi][n8][half * 2 + 0] * mv;
                        o.y = acc[mi][n8][half * 2 + 1] * mv;
                        *reinterpret_cast<float2*>(cp + n8 * 8) = o;
                    }
                }
            }
        }
        __syncthreads();   // epilogue mask reads done before next convert overwrites
    }
}

extern "C" void kernel_launch(void* const* d_in, const int* in_sizes, int n_in,
                              void* d_out, int out_size)
{
    const float* x = (const float*)d_in[0];          // [100000, 128]
    const float* w = (const float*)d_in[1];          // [128, 128]
    // d_in[2] = att — softmax weights sum to 1 per destination segment and
    // multiply that segment's own features => mathematically irrelevant.
    const int* edge_index = (const int*)d_in[3];     // [2, 1600000] int32
    const int* col = edge_index + N_EDGES;           // edge_index[1]
    float* out = (float*)d_out;

    static bool attr_set = false;
    if (!attr_set) {
        cudaFuncSetAttribute(gat_gemm_mma,
                             cudaFuncAttributeMaxDynamicSharedMemorySize, SM_TOTAL);
        attr_set = true;
    }

    mask_scatter_kernel<<<148, NT>>>(col, w);
    gat_gemm_mma<<<GRID_P, NT, SM_TOTAL>>>(x, out);
}